// round 3
// baseline (speedup 1.0000x reference)
#include <cuda_runtime.h>
#include <math.h>

#define N_TOK 8192   // B*H*W
#define EDIM  256
#define CDIM  512
#define KCODE 8192

// ---------------- device scratch (static, no allocation) ----------------
__device__ float g_ze [N_TOK * EDIM];   // z_e row-major [n][e]   (8 MB)
__device__ float g_zeT[EDIM * N_TOK];   // z_e transposed [e][n]  (8 MB)
__device__ float g_c  [KCODE];          // ||e_k||^2  (XLA-reduce emulated)
__device__ float g_R  [N_TOK];          // ||x_n||^2  (XLA-reduce emulated)
__device__ unsigned long long g_best[N_TOK];
__device__ double g_diffsum;

// ---------------- helpers ----------------
// pack for atomicMax so that SMALLER dist wins; equal dist -> SMALLER k wins
__device__ __forceinline__ unsigned long long pack_min(float dist, int k) {
    unsigned int b = ~__float_as_uint(dist);       // dist > 0 always; ~bits is monotone decreasing
    return ((unsigned long long)b << 32) | (unsigned int)(8191 - k);
}

__device__ __forceinline__ unsigned long long dup2(float x) {
    unsigned long long r;
    asm("mov.b64 %0, {%1, %1};" : "=l"(r) : "r"(__float_as_uint(x)));
    return r;
}

#define FMA2(d, a, b) asm("fma.rn.f32x2 %0, %1, %2, %0;" : "+l"(d) : "l"(a), "l"(b))

// XLA-GPU style row reduce of squares over 256 contiguous floats.
// 1 warp per row, x2 vectorized: lane t handles elements {64j+2t, 64j+2t+1}, j=0..3,
// accumulated in address order with separate mul/add (no fma contraction),
// then shfl_down tree 16,8,4,2,1. Result on lane 0.
__device__ __forceinline__ float row_sumsq_xla(const float* __restrict__ row, int lane) {
    float acc = 0.f;
#pragma unroll
    for (int j = 0; j < 4; j++) {
        float2 v = *(const float2*)(row + j * 64 + 2 * lane);
        acc = __fadd_rn(acc, __fmul_rn(v.x, v.x));
        acc = __fadd_rn(acc, __fmul_rn(v.y, v.y));
    }
#pragma unroll
    for (int o = 16; o; o >>= 1)
        acc = __fadd_rn(acc, __shfl_down_sync(0xffffffffu, acc, o));
    return acc;  // valid on lane 0
}

// ---------------- kernels ----------------
__global__ void reset_kernel() {
    int i = blockIdx.x * blockDim.x + threadIdx.x;
    if (i < N_TOK) g_best[i] = 0ULL;
    if (i == 0) g_diffsum = 0.0;
}

// g_c[k] = ||e_k||^2  (emulated XLA reduce)
__global__ void c_kernel(const float* __restrict__ embed) {
    int k    = blockIdx.x * 8 + (threadIdx.x >> 5);
    int lane = threadIdx.x & 31;
    float s = row_sumsq_xla(embed + (size_t)k * EDIM, lane);
    if (lane == 0) g_c[k] = s;
}

// g_R[n] = ||z_e[n]||^2  (emulated XLA reduce)
__global__ void R_kernel() {
    int n    = blockIdx.x * 8 + (threadIdx.x >> 5);
    int lane = threadIdx.x & 31;
    float s = row_sumsq_xla(g_ze + (size_t)n * EDIM, lane);
    if (lane == 0) g_R[n] = s;
}

// z_e[n][e] = seq-FFMA over c=0..511 of z*w, + bias (matches ascending-k GEMM rounding).
// Tiles: 64 n x 64 e, BK=16. 256 threads, 4x4 microtile.
__global__ __launch_bounds__(256) void proj_kernel(const float* __restrict__ z,
                                                   const float* __restrict__ w,
                                                   const float* __restrict__ bias) {
    __shared__ float As[16][64];
    __shared__ float Ws[16][64];
    int t  = threadIdx.x;
    int n0 = blockIdx.x * 64;
    int e0 = blockIdx.y * 64;
    int b   = n0 >> 10;
    int hw0 = n0 & 1023;
    const float* zb = z + (size_t)b * CDIM * 1024 + hw0;

    int tx = t & 15, ty = t >> 4;
    int a_c = t >> 6;          // 0..3
    int a_n = t & 63;
    int w_e = t >> 2;          // 0..63
    int w_c = (t & 3) * 4;

    float acc[4][4] = {};
    for (int c0 = 0; c0 < CDIM; c0 += 16) {
        __syncthreads();
#pragma unroll
        for (int p = 0; p < 4; p++) {
            int cl = p * 4 + a_c;
            As[cl][a_n] = zb[(size_t)(c0 + cl) * 1024 + a_n];
        }
        float4 wv = *(const float4*)&w[(size_t)(e0 + w_e) * CDIM + c0 + w_c];
        Ws[w_c + 0][w_e] = wv.x; Ws[w_c + 1][w_e] = wv.y;
        Ws[w_c + 2][w_e] = wv.z; Ws[w_c + 3][w_e] = wv.w;
        __syncthreads();
#pragma unroll
        for (int kk = 0; kk < 16; kk++) {
            float4 av = *(const float4*)&As[kk][ty * 4];
            float4 bv = *(const float4*)&Ws[kk][tx * 4];
            float a[4] = {av.x, av.y, av.z, av.w};
            float c[4] = {bv.x, bv.y, bv.z, bv.w};
#pragma unroll
            for (int i = 0; i < 4; i++)
#pragma unroll
                for (int j = 0; j < 4; j++) acc[i][j] = __fmaf_rn(a[i], c[j], acc[i][j]);
        }
    }
    float4 b4 = *(const float4*)&bias[e0 + tx * 4];
    float bb[4] = {b4.x, b4.y, b4.z, b4.w};
#pragma unroll
    for (int i = 0; i < 4; i++) {
        int n = n0 + ty * 4 + i;
        float o0 = __fadd_rn(acc[i][0], bb[0]), o1 = __fadd_rn(acc[i][1], bb[1]);
        float o2 = __fadd_rn(acc[i][2], bb[2]), o3 = __fadd_rn(acc[i][3], bb[3]);
        float4 o = make_float4(o0, o1, o2, o3);
        *(float4*)&g_ze[(size_t)n * EDIM + e0 + tx * 4] = o;
        g_zeT[(size_t)(e0 + tx * 4 + 0) * N_TOK + n] = o0;
        g_zeT[(size_t)(e0 + tx * 4 + 1) * N_TOK + n] = o1;
        g_zeT[(size_t)(e0 + tx * 4 + 2) * N_TOK + n] = o2;
        g_zeT[(size_t)(e0 + tx * 4 + 3) * N_TOK + n] = o3;
    }
}

// Fused M GEMM (ascending-k seq FFMA) + dist = fl(fl(R - 2M) + c) + argmin(first index).
#define SCORE_SMEM ((256 * 128 + 16 * 128 + 128) * 4)

__global__ __launch_bounds__(256) void score_kernel(const float* __restrict__ embed) {
    extern __shared__ float smem[];
    float* Xsm = smem;                     // [256][128]
    float* Es  = smem + 256 * 128;         // [16][128]
    float* Rs  = smem + 256 * 128 + 16 * 128;  // [128]
    int t  = threadIdx.x;
    int n0 = blockIdx.x * 128;
    int ks0 = blockIdx.y * 512;

    // stage X panel (Xsm[c*128+n]) and R
#pragma unroll 4
    for (int i = 0; i < 32; i++) {
        int idx = t + i * 256;
        int c   = idx >> 5;
        int n4  = (idx & 31) * 4;
        float4 v = *(const float4*)&g_zeT[(size_t)c * N_TOK + n0 + n4];
        *(float4*)&Xsm[c * 128 + n4] = v;
    }
    if (t < 128) Rs[t] = g_R[n0 + t];
    __syncthreads();

    int tx = t & 15, ty = t >> 4;
    float bdd[8]; int bkk[8];
    float Rrow[8];
#pragma unroll
    for (int i = 0; i < 8; i++) {
        bdd[i] = 3.0e38f; bkk[i] = 0;
        Rrow[i] = Rs[ty * 8 + i];
    }

    int e_k = t >> 1;            // code row within 128-tile
    int e_c = (t & 1) * 8;

#pragma unroll 1
    for (int kt = 0; kt < 4; kt++) {
        int k0 = ks0 + kt * 128;
        unsigned long long acc[8][4];
#pragma unroll
        for (int ii = 0; ii < 8; ii++)
#pragma unroll
            for (int jj = 0; jj < 4; jj++) acc[ii][jj] = 0ULL;

        const float* erow = embed + (size_t)(k0 + e_k) * EDIM + e_c;
        float4 r0 = *(const float4*)(erow);
        float4 r1 = *(const float4*)(erow + 4);

#pragma unroll 1
        for (int ks = 0; ks < 16; ks++) {
            __syncthreads();
            Es[(e_c + 0) * 128 + e_k] = r0.x; Es[(e_c + 1) * 128 + e_k] = r0.y;
            Es[(e_c + 2) * 128 + e_k] = r0.z; Es[(e_c + 3) * 128 + e_k] = r0.w;
            Es[(e_c + 4) * 128 + e_k] = r1.x; Es[(e_c + 5) * 128 + e_k] = r1.y;
            Es[(e_c + 6) * 128 + e_k] = r1.z; Es[(e_c + 7) * 128 + e_k] = r1.w;
            __syncthreads();
            if (ks < 15) {
                const float* p = erow + (ks + 1) * 16;
                r0 = *(const float4*)p;
                r1 = *(const float4*)(p + 4);
            }
#pragma unroll
            for (int kk = 0; kk < 16; kk++) {
                const float4* xp = (const float4*)&Xsm[(ks * 16 + kk) * 128 + ty * 8];
                float4 a0 = xp[0], a1 = xp[1];
                const ulonglong2* bp = (const ulonglong2*)&Es[kk * 128 + tx * 8];
                ulonglong2 q0 = bp[0], q1 = bp[1];
                unsigned long long bb[4] = {q0.x, q0.y, q1.x, q1.y};
                unsigned long long ad[8];
                ad[0] = dup2(a0.x); ad[1] = dup2(a0.y); ad[2] = dup2(a0.z); ad[3] = dup2(a0.w);
                ad[4] = dup2(a1.x); ad[5] = dup2(a1.y); ad[6] = dup2(a1.z); ad[7] = dup2(a1.w);
#pragma unroll
                for (int ii = 0; ii < 8; ii++)
#pragma unroll
                    for (int jj = 0; jj < 4; jj++) FMA2(acc[ii][jj], ad[ii], bb[jj]);
            }
        }
        // epilogue: dist = fl(fl(R - 2M) + c), running argmin, ascending k -> strict <
#pragma unroll
        for (int jj = 0; jj < 4; jj++) {
#pragma unroll
            for (int half = 0; half < 2; half++) {
                int j = jj * 2 + half;
                int kidx = k0 + tx * 8 + j;
                float ck = __ldg(&g_c[kidx]);
#pragma unroll
                for (int ii = 0; ii < 8; ii++) {
                    unsigned int bits = half ? (unsigned int)(acc[ii][jj] >> 32)
                                             : (unsigned int)(acc[ii][jj] & 0xffffffffULL);
                    float M = __uint_as_float(bits);
                    float d1 = __fsub_rn(Rrow[ii], 2.0f * M);   // fl(R - 2M), 2M exact
                    float dist = __fadd_rn(d1, ck);             // fl(.. + c)
                    if (dist < bdd[ii]) { bdd[ii] = dist; bkk[ii] = kidx; }
                }
            }
        }
    }

    // CTA reduction across the 16 column-threads of each row
    __syncthreads();
    float* sv = smem;                 // 16*128 floats
    int*   sk = (int*)(smem + 2048);  // 16*128 ints
#pragma unroll
    for (int ii = 0; ii < 8; ii++) {
        int row = ty * 8 + ii;
        sv[tx * 128 + row] = bdd[ii];
        sk[tx * 128 + row] = bkk[ii];
    }
    __syncthreads();
    if (t < 128) {
        float best = 3.0e38f; int bidx = 0x7fffffff;
#pragma unroll
        for (int x = 0; x < 16; x++) {
            float v = sv[x * 128 + t];
            int   k = sk[x * 128 + t];
            if (v < best || (v == best && k < bidx)) { best = v; bidx = k; }
        }
        atomicMax(&g_best[n0 + t], pack_min(best, bidx));
    }
}

// gather z_q, write output, accumulate commitment-loss sum, write indices
__global__ void finalize_kernel(const float* __restrict__ embed,
                                float* __restrict__ out, int out_size) {
    int n = blockIdx.x, t = threadIdx.x;
    unsigned long long p = g_best[n];
    int k = 8191 - (int)(p & 0xffffffffu);
    float zq = embed[(size_t)k * EDIM + t];
    float ze = g_ze[(size_t)n * EDIM + t];
    out[(size_t)n * EDIM + t] = zq;
    float d = zq - ze;
    float s = d * d;
#pragma unroll
    for (int o = 16; o; o >>= 1) s += __shfl_down_sync(0xffffffffu, s, o);
    __shared__ float red[8];
    if ((t & 31) == 0) red[t >> 5] = s;
    __syncthreads();
    if (t == 0) {
        float v = red[0] + red[1] + red[2] + red[3] + red[4] + red[5] + red[6] + red[7];
        atomicAdd(&g_diffsum, (double)v);
        if (out_size >= N_TOK * EDIM + 1 + N_TOK)
            out[N_TOK * EDIM + 1 + n] = (float)k;
    }
}

__global__ void diff_kernel(float* __restrict__ out, int out_size) {
    if (out_size > N_TOK * EDIM)
        out[N_TOK * EDIM] = (float)(g_diffsum / (double)(N_TOK * EDIM));
}

// ---------------- launch ----------------
extern "C" void kernel_launch(void* const* d_in, const int* in_sizes, int n_in,
                              void* d_out, int out_size) {
    const float* z     = (const float*)d_in[0];   // [8,512,32,32]
    const float* pw    = (const float*)d_in[1];   // [256,512]
    const float* pb    = (const float*)d_in[2];   // [256]
    const float* embed = (const float*)d_in[3];   // [8192,256]
    float* out = (float*)d_out;

    cudaFuncSetAttribute(score_kernel, cudaFuncAttributeMaxDynamicSharedMemorySize, SCORE_SMEM);

    reset_kernel<<<32, 256>>>();
    c_kernel<<<KCODE / 8, 256>>>(embed);
    proj_kernel<<<dim3(128, 4), 256>>>(z, pw, pb);
    R_kernel<<<N_TOK / 8, 256>>>();
    score_kernel<<<dim3(64, 16), 256, SCORE_SMEM>>>(embed);
    finalize_kernel<<<N_TOK, 256>>>(embed, out, out_size);
    diff_kernel<<<1, 1>>>(out, out_size);
}